// round 11
// baseline (speedup 1.0000x reference)
#include <cuda_runtime.h>
#include <cuda_fp16.h>
#include <cuda_bf16.h>
#include <cstdint>

#define BB   8
#define SS   2048
#define DIMV 2048
#define HDV  128
#define MTOK (BB*SS)        // 16384 tokens
#define NQKV 384            // q|k|v concat width
#define SPLIT_SCALE 2048.0f
#define INV_SPLIT   4.8828125e-4f   // 1/2048
#define SCAN_CH 16                   // scan chunk (steps)
#define NCHUNK (SS / SCAN_CH)        // 128
#define NPART  4                     // scan sequence parts
#define PCH    (NCHUNK / NPART)      // 32 chunks per part

// ---------------------------------------------------------------------------
// Scratch (device globals; no allocation allowed)
// ---------------------------------------------------------------------------
__device__ __half g_xh[MTOK * DIMV];
__device__ __half g_xl[MTOK * DIMV];
__device__ __half g_wqkvh[NQKV * DIMV];   // [384][2048] K-major
__device__ __half g_wqkvl[NQKV * DIMV];
__device__ __nv_bfloat16 g_woh[DIMV * HDV];  // [2048][128] K-major
__device__ __nv_bfloat16 g_wol[DIMV * HDV];
__device__ float g_bqkv[NQKV];
__device__ float g_qkv[MTOK * NQKV];      // [token][384] = q|k|v
__device__ __nv_bfloat16 g_yh[MTOK * HDV], g_yl[MTOK * HDV];
__device__ float g_wfin_scratch[BB * HDV * HDV];
__device__ float g_G[BB * NCHUNK * 512];  // per chunk: [256]=Gkk, [256]=Gqk

// ---------------------------------------------------------------------------
// Helpers
// ---------------------------------------------------------------------------
__device__ __forceinline__ uint32_t smem_to_u32(const void* p) {
    uint32_t a;
    asm("{ .reg .u64 t; cvta.to.shared.u64 t, %1; cvt.u32.u64 %0, t; }"
        : "=r"(a) : "l"(p));
    return a;
}

#define SMEM_SWIZZLE_128B(off) ((off) ^ (((off) >> 3) & 0x70))

#define CP_ASYNC_CG(dst, src) \
    asm volatile("cp.async.cg.shared.global [%0], [%1], 16;" \
        :: "r"(dst), "l"(src) : "memory")
#define CP_COMMIT() asm volatile("cp.async.commit_group;" ::: "memory")
#define CP_WAIT_1() asm volatile("cp.async.wait_group 1;" ::: "memory")
#define CP_WAIT_0() asm volatile("cp.async.wait_group 0;" ::: "memory")

__device__ __forceinline__ void ldsm_x4(uint32_t (&r)[4], uint32_t addr) {
    asm volatile("ldmatrix.sync.aligned.m8n8.x4.shared.b16 {%0,%1,%2,%3}, [%4];"
        : "=r"(r[0]), "=r"(r[1]), "=r"(r[2]), "=r"(r[3]) : "r"(addr));
}

template <bool BF16>
__device__ __forceinline__ void mma_16(float (&c)[4], const uint32_t (&a)[4],
                                       const uint32_t b0, const uint32_t b1) {
    if (BF16)
        asm volatile("mma.sync.aligned.m16n8k16.row.col.f32.bf16.bf16.f32 "
            "{%0,%1,%2,%3}, {%4,%5,%6,%7}, {%8,%9}, {%0,%1,%2,%3};"
            : "+f"(c[0]), "+f"(c[1]), "+f"(c[2]), "+f"(c[3])
            : "r"(a[0]), "r"(a[1]), "r"(a[2]), "r"(a[3]), "r"(b0), "r"(b1));
    else
        asm volatile("mma.sync.aligned.m16n8k16.row.col.f32.f16.f16.f32 "
            "{%0,%1,%2,%3}, {%4,%5,%6,%7}, {%8,%9}, {%0,%1,%2,%3};"
            : "+f"(c[0]), "+f"(c[1]), "+f"(c[2]), "+f"(c[3])
            : "r"(a[0]), "r"(a[1]), "r"(a[2]), "r"(a[3]), "r"(b0), "r"(b1));
}

// ---------------------------------------------------------------------------
// splits
// ---------------------------------------------------------------------------
__device__ __forceinline__ void split2f(float x, unsigned short& h, unsigned short& l) {
    __half hh = __float2half_rn(x);
    float r = (x - __half2float(hh)) * SPLIT_SCALE;
    h = __half_as_ushort(hh);
    l = __half_as_ushort(__float2half_rn(r));
}
__device__ __forceinline__ void split2b(float x, unsigned short& h, unsigned short& l) {
    __nv_bfloat16 hh = __float2bfloat16(x);
    float r = x - __bfloat162float(hh);
    h = __bfloat16_as_ushort(hh);
    l = __bfloat16_as_ushort(__float2bfloat16(r));
}

__global__ __launch_bounds__(256) void split2f_kernel(
    const float* __restrict__ in, __half* __restrict__ h,
    __half* __restrict__ l, int n4)
{
    int i = blockIdx.x * 256 + threadIdx.x;
    if (i >= n4) return;
    float4 x = reinterpret_cast<const float4*>(in)[i];
    ushort4 H, L;
    split2f(x.x, H.x, L.x); split2f(x.y, H.y, L.y);
    split2f(x.z, H.z, L.z); split2f(x.w, H.w, L.w);
    reinterpret_cast<ushort4*>(h)[i] = H;
    reinterpret_cast<ushort4*>(l)[i] = L;
}

__global__ __launch_bounds__(256) void transpose_split2f_kernel(
    const float* __restrict__ in, __half* __restrict__ h,
    __half* __restrict__ l, int K, int N)
{
    int idx = blockIdx.x * 256 + threadIdx.x;
    if (idx >= K * N) return;
    int k = idx / N, n = idx - k * N;
    unsigned short H, L;
    split2f(in[idx], H, L);
    size_t o = (size_t)n * K + k;
    h[o] = __ushort_as_half(H);
    l[o] = __ushort_as_half(L);
}

__global__ __launch_bounds__(256) void transpose_split2b_kernel(
    const float* __restrict__ in, __nv_bfloat16* __restrict__ h,
    __nv_bfloat16* __restrict__ l, int K, int N)
{
    int idx = blockIdx.x * 256 + threadIdx.x;
    if (idx >= K * N) return;
    int k = idx / N, n = idx - k * N;
    unsigned short H, L;
    split2b(in[idx], H, L);
    size_t o = (size_t)n * K + k;
    h[o] = __ushort_as_bfloat16(H);
    l[o] = __ushort_as_bfloat16(L);
}

__global__ void concat_bias_kernel(const float* __restrict__ a,
                                   const float* __restrict__ b,
                                   const float* __restrict__ c,
                                   float* __restrict__ o)
{
    int t = threadIdx.x;
    if (t < HDV) { o[t] = a[t]; o[HDV + t] = b[t]; o[2 * HDV + t] = c[t]; }
}

// ---------------------------------------------------------------------------
// HMMA GEMM, 2-way split operands. part_off < 0: m0 = bx*128 (linear).
// part_off >= 0 (out-GEMM token-part): m0 = (bx>>2)*2048 + part_off + (bx&3)*128.
// ---------------------------------------------------------------------------
#define TILE_B   16384
#define STAGE_B  (4 * TILE_B)
#define SMEM_GEMM (2 * STAGE_B)

template <bool BF16>
__global__ __launch_bounds__(256) void mma_gemm(
    const void* __restrict__ A0v, const void* __restrict__ A1v,
    const void* __restrict__ B0v, const void* __restrict__ B1v,
    const float* __restrict__ bias, float* __restrict__ O,
    int N, int K, int part_off)
{
    const float mergeScale = BF16 ? 1.0f : INV_SPLIT;
    extern __shared__ char smem[];
    const uint32_t sbase = smem_to_u32(smem);
    const int tid = threadIdx.x;
    const int lane = tid & 31, wid = tid >> 5;
    const int warp_m = wid & 3;
    const int warp_n = wid >> 2;
    int m0;
    if (part_off < 0) m0 = blockIdx.x * 128;
    else m0 = ((blockIdx.x >> 2) << 11) + part_off + ((blockIdx.x & 3) << 7);
    const int n0 = blockIdx.y * 128;
    const int NC = K >> 6;

    const uint16_t* src[4] = {
        (const uint16_t*)A0v + (size_t)m0 * K, (const uint16_t*)A1v + (size_t)m0 * K,
        (const uint16_t*)B0v + (size_t)n0 * K, (const uint16_t*)B1v + (size_t)n0 * K };

    const int lrow = tid >> 1;
    const int lhalf = tid & 1;

    float master[2][8][4];
#pragma unroll
    for (int a = 0; a < 2; a++)
#pragma unroll
        for (int b = 0; b < 8; b++)
#pragma unroll
            for (int c = 0; c < 4; c++) master[a][b][c] = 0.0f;

    auto load_stage = [&](int buf, int chunk) {
        const int kc = chunk << 6;
        const uint32_t sb = sbase + buf * STAGE_B;
#pragma unroll
        for (int t = 0; t < 4; t++) {
            const char* g = (const char*)(src[t] + (size_t)lrow * K + kc) + lhalf * 64;
            const uint32_t tb = sb + t * TILE_B;
#pragma unroll
            for (int i = 0; i < 4; i++) {
                uint32_t off = (uint32_t)(lrow * 128 + lhalf * 64 + i * 16);
                CP_ASYNC_CG(tb + SMEM_SWIZZLE_128B(off), g + i * 16);
            }
        }
    };

    load_stage(0, 0);
    CP_COMMIT();

    float chunk[2][8][4];

    for (int c = 0; c < NC; c++) {
        const int s = c & 1;
        if (c + 1 < NC) { load_stage(s ^ 1, c + 1); CP_COMMIT(); CP_WAIT_1(); }
        else            { CP_WAIT_0(); }
        __syncthreads();

        const uint32_t base = sbase + s * STAGE_B;

        // ---- pass A: mixed products (h*l + l*h) ----
#pragma unroll
        for (int a = 0; a < 2; a++)
#pragma unroll
            for (int b = 0; b < 8; b++)
#pragma unroll
                for (int cc = 0; cc < 4; cc++) chunk[a][b][cc] = 0.0f;

#pragma unroll
        for (int kk = 0; kk < 4; kk++) {
            uint32_t ah[2][4], al[2][4];
#pragma unroll
            for (int mt = 0; mt < 2; mt++) {
                int row = warp_m * 32 + mt * 16 + (lane & 15);
                int col = kk * 32 + ((lane >> 4) << 4);
                uint32_t off = SMEM_SWIZZLE_128B((uint32_t)(row * 128 + col));
                ldsm_x4(ah[mt], base + off);
                ldsm_x4(al[mt], base + TILE_B + off);
            }
#pragma unroll
            for (int p = 0; p < 4; p++) {
                int row = warp_n * 64 + p * 16 + (lane & 7) + (((lane >> 4) & 1) << 3);
                int col = kk * 32 + (((lane >> 3) & 1) << 4);
                uint32_t off = SMEM_SWIZZLE_128B((uint32_t)(row * 128 + col));
                uint32_t bh[4], bl[4];
                ldsm_x4(bh, base + 2 * TILE_B + off);
                ldsm_x4(bl, base + 3 * TILE_B + off);
#pragma unroll
                for (int mt = 0; mt < 2; mt++)
#pragma unroll
                    for (int n2 = 0; n2 < 2; n2++) {
                        mma_16<BF16>(chunk[mt][2 * p + n2], ah[mt], bl[2 * n2], bl[2 * n2 + 1]);
                        mma_16<BF16>(chunk[mt][2 * p + n2], al[mt], bh[2 * n2], bh[2 * n2 + 1]);
                    }
            }
        }
#pragma unroll
        for (int a = 0; a < 2; a++)
#pragma unroll
            for (int b = 0; b < 8; b++)
#pragma unroll
                for (int cc = 0; cc < 4; cc++)
                    master[a][b][cc] = fmaf(chunk[a][b][cc], mergeScale, master[a][b][cc]);

        // ---- pass B: h*h ----
#pragma unroll
        for (int a = 0; a < 2; a++)
#pragma unroll
            for (int b = 0; b < 8; b++)
#pragma unroll
                for (int cc = 0; cc < 4; cc++) chunk[a][b][cc] = 0.0f;

#pragma unroll
        for (int kk = 0; kk < 4; kk++) {
            uint32_t ah[2][4];
#pragma unroll
            for (int mt = 0; mt < 2; mt++) {
                int row = warp_m * 32 + mt * 16 + (lane & 15);
                int col = kk * 32 + ((lane >> 4) << 4);
                uint32_t off = SMEM_SWIZZLE_128B((uint32_t)(row * 128 + col));
                ldsm_x4(ah[mt], base + off);
            }
#pragma unroll
            for (int p = 0; p < 4; p++) {
                int row = warp_n * 64 + p * 16 + (lane & 7) + (((lane >> 4) & 1) << 3);
                int col = kk * 32 + (((lane >> 3) & 1) << 4);
                uint32_t off = SMEM_SWIZZLE_128B((uint32_t)(row * 128 + col));
                uint32_t bh[4];
                ldsm_x4(bh, base + 2 * TILE_B + off);
#pragma unroll
                for (int mt = 0; mt < 2; mt++)
#pragma unroll
                    for (int n2 = 0; n2 < 2; n2++)
                        mma_16<BF16>(chunk[mt][2 * p + n2], ah[mt], bh[2 * n2], bh[2 * n2 + 1]);
            }
        }
#pragma unroll
        for (int a = 0; a < 2; a++)
#pragma unroll
            for (int b = 0; b < 8; b++)
#pragma unroll
                for (int cc = 0; cc < 4; cc++) master[a][b][cc] += chunk[a][b][cc];

        __syncthreads();
    }

    // ---- epilogue ----
    float2 bcol[8];
#pragma unroll
    for (int nt = 0; nt < 8; nt++) {
        int cbase = n0 + warp_n * 64 + nt * 8 + (lane & 3) * 2;
        bcol[nt].x = __ldg(bias + cbase);
        bcol[nt].y = __ldg(bias + cbase + 1);
    }
#pragma unroll
    for (int mt = 0; mt < 2; mt++) {
        int r0 = m0 + warp_m * 32 + mt * 16 + (lane >> 2);
#pragma unroll
        for (int nt = 0; nt < 8; nt++) {
            int cbase = n0 + warp_n * 64 + nt * 8 + (lane & 3) * 2;
            float2 v0 = { master[mt][nt][0] + bcol[nt].x, master[mt][nt][1] + bcol[nt].y };
            float2 v1 = { master[mt][nt][2] + bcol[nt].x, master[mt][nt][3] + bcol[nt].y };
            *reinterpret_cast<float2*>(O + (size_t)r0 * N + cbase) = v0;
            *reinterpret_cast<float2*>(O + (size_t)(r0 + 8) * N + cbase) = v1;
        }
    }
}

// ---------------------------------------------------------------------------
// Gram kernel (R9): Gkk[u][t]=k_u.k_t, Gqk[u][t]=k_u.q_t per (batch, chunk).
// ---------------------------------------------------------------------------
__global__ __launch_bounds__(256) void gram_kernel(
    const float* __restrict__ qkv, float* __restrict__ G)
{
    const int blk = blockIdx.x;               // b*NCHUNK + c
    const int b = blk >> 7, c = blk & (NCHUNK - 1);
    const int u = threadIdx.x >> 4, t = threadIdx.x & 15;
    const float* basep = qkv + ((size_t)b * SS + c * SCAN_CH) * NQKV;
    const float4* ku = (const float4*)(basep + u * NQKV + 128);
    const float4* kt = (const float4*)(basep + t * NQKV + 128);
    const float4* qt = (const float4*)(basep + t * NQKV);
    float skk = 0.0f, sqk = 0.0f;
#pragma unroll 8
    for (int j = 0; j < 32; j++) {
        float4 a = __ldg(ku + j), bk = __ldg(kt + j), bq = __ldg(qt + j);
        skk += a.x * bk.x + a.y * bk.y + a.z * bk.z + a.w * bk.w;
        sqk += a.x * bq.x + a.y * bq.y + a.z * bq.z + a.w * bq.w;
    }
    float* go = G + (size_t)blk * 512;
    go[u * 16 + t] = skk;
    go[256 + u * 16 + t] = sqk;
}

// ---------------------------------------------------------------------------
// Chunked delta-rule scan (R9 math), SEQUENCE-SPLIT: processes chunks
// [c0, c0+PCH). W loaded from wsrc (state for part 0, wfin checkpoint after),
// saved to wfin at part end. y written directly as bf16 2-way split.
// ---------------------------------------------------------------------------
#define QKV_F   (SCAN_CH * NQKV)             // 6144 floats
#define STAGE_F (QKV_F + 512)
#define SCAN_SMEM (2 * STAGE_F * 4)          // 53248 bytes

__global__ __launch_bounds__(256) void titan_scan(
    const float* __restrict__ qkv, const float* __restrict__ G,
    const float* __restrict__ wsrc, const float* __restrict__ lr_ptr,
    __nv_bfloat16* __restrict__ yh, __nv_bfloat16* __restrict__ yl,
    float* __restrict__ wfin, int c0)
{
    extern __shared__ float smemf[];
    const int tid  = threadIdx.x;
    const int warp = tid >> 5;
    const int lane = tid & 31;
    const int b    = blockIdx.x >> 4;
    const int i    = ((blockIdx.x & 15) << 3) + warp;

    const float lr = *lr_ptr;
    const float* base  = qkv + (size_t)b * SS * NQKV;
    const float* gbase = G + (size_t)b * NCHUNK * 512;
    __nv_bfloat16* yhb = yh + (size_t)b * SS * HDV + i;
    __nv_bfloat16* ylb = yl + (size_t)b * SS * HDV + i;

    const uint32_t s0 = smem_to_u32(smemf);
    auto stage = [&](int c) {
        if (c < c0 + PCH + 2 && c < NCHUNK) {
            const char* g = (const char*)(base + (size_t)c * QKV_F);
            const uint32_t sb = s0 + (uint32_t)(c & 1) * (STAGE_F * 4);
#pragma unroll
            for (int it = 0; it < 6; it++) {
                int idx = tid + it * 256;
                CP_ASYNC_CG(sb + idx * 16, g + idx * 16);
            }
            if (tid < 128)
                CP_ASYNC_CG(sb + QKV_F * 4 + tid * 16,
                            (const char*)(gbase + (size_t)c * 512) + tid * 16);
        }
    };
    stage(c0); CP_COMMIT();
    stage(c0 + 1); CP_COMMIT();

    float4 w4 = *reinterpret_cast<const float4*>(
        wsrc + ((size_t)b * HDV + i) * HDV + lane * 4);

    for (int c = c0; c < c0 + PCH; c++) {
        CP_WAIT_1();
        __syncthreads();
        const float* sb  = smemf + (c & 1) * STAGE_F;
        const float* gkk = sb + QKV_F;
        const float* gqk = gkk + 256;

        float Bv[SCAN_CH], e[SCAN_CH];
        float Asel = 0.0f;

        // ---- P1: parallel W0 dots ----
#pragma unroll
        for (int t = 0; t < SCAN_CH; t++) {
            const float* row = sb + t * NQKV;
            float4 q = *reinterpret_cast<const float4*>(row + lane * 4);
            float4 k = *reinterpret_cast<const float4*>(row + 128 + lane * 4);
            float a  = w4.x * q.x + w4.y * q.y + w4.z * q.z + w4.w * q.w;
            float bb = w4.x * k.x + w4.y * k.y + w4.z * k.z + w4.w * k.w;
#pragma unroll
            for (int o = 16; o > 0; o >>= 1) {
                a  += __shfl_xor_sync(0xffffffffu, a,  o);
                bb += __shfl_xor_sync(0xffffffffu, bb, o);
            }
            Bv[t] = bb;
            if (lane == t) Asel = a;
        }

        // ---- P2: serial triangular recursion (all lanes redundant) ----
#pragma unroll
        for (int t = 0; t < SCAN_CH; t++) {
            float acc = Bv[t];
#pragma unroll
            for (int u = 0; u < SCAN_CH; u++)
                if (u < t) acc = fmaf(-e[u], gkk[u * 16 + t], acc);
            e[t] = lr * (acc - sb[t * NQKV + 256 + i]);
        }

        // ---- P3a: outputs, fused bf16 split ----
        if (lane < SCAN_CH) {
            float dq = Asel;
#pragma unroll
            for (int u = 0; u < SCAN_CH - 1; u++)
                if (u < lane) dq = fmaf(-e[u], gqk[u * 16 + lane], dq);
            unsigned short H, L;
            split2b(dq, H, L);
            size_t off = (size_t)(c * SCAN_CH + lane) * HDV;
            yhb[off] = __ushort_as_bfloat16(H);
            ylb[off] = __ushort_as_bfloat16(L);
        }

        // ---- P3b: W update ----
#pragma unroll
        for (int u = 0; u < SCAN_CH; u++) {
            float4 k = *reinterpret_cast<const float4*>(sb + u * NQKV + 128 + lane * 4);
            w4.x = fmaf(-e[u], k.x, w4.x);
            w4.y = fmaf(-e[u], k.y, w4.y);
            w4.z = fmaf(-e[u], k.z, w4.z);
            w4.w = fmaf(-e[u], k.w, w4.w);
        }

        __syncthreads();
        stage(c + 2); CP_COMMIT();
    }

    *reinterpret_cast<float4*>(wfin + ((size_t)b * HDV + i) * HDV + lane * 4) = w4;
}

// ---------------------------------------------------------------------------
// Launch: stream-forked graph. s1 (non-blocking) runs weight prep, then the
// out-GEMM token-parts as scan parts complete on the main stream.
// ---------------------------------------------------------------------------
extern "C" void kernel_launch(void* const* d_in, const int* in_sizes, int n_in,
                              void* d_out, int out_size)
{
    const float* x     = (const float*)d_in[0];
    const float* state = (const float*)d_in[1];
    const float* Wq    = (const float*)d_in[2];
    const float* bq    = (const float*)d_in[3];
    const float* Wk    = (const float*)d_in[4];
    const float* bk    = (const float*)d_in[5];
    const float* Wv    = (const float*)d_in[6];
    const float* bv    = (const float*)d_in[7];
    const float* Wo    = (const float*)d_in[8];
    const float* bo    = (const float*)d_in[9];
    const float* lr    = (const float*)d_in[10];
    float* out = (float*)d_out;

    __half *xh, *xl, *wqkvh, *wqkvl;
    __nv_bfloat16 *yh, *yl, *woh, *wol;
    float *bqkv, *gqkv, *gws, *gG;
    cudaGetSymbolAddress((void**)&xh, g_xh);
    cudaGetSymbolAddress((void**)&xl, g_xl);
    cudaGetSymbolAddress((void**)&yh, g_yh);
    cudaGetSymbolAddress((void**)&yl, g_yl);
    cudaGetSymbolAddress((void**)&wqkvh, g_wqkvh);
    cudaGetSymbolAddress((void**)&wqkvl, g_wqkvl);
    cudaGetSymbolAddress((void**)&woh, g_woh);
    cudaGetSymbolAddress((void**)&wol, g_wol);
    cudaGetSymbolAddress((void**)&bqkv, g_bqkv);
    cudaGetSymbolAddress((void**)&gqkv, g_qkv);
    cudaGetSymbolAddress((void**)&gws, g_wfin_scratch);
    cudaGetSymbolAddress((void**)&gG, g_G);

    const size_t out_elems  = (size_t)BB * SS * DIMV;
    const size_t wfin_elems = (size_t)BB * HDV * HDV;
    float* wfin = ((size_t)out_size >= out_elems + wfin_elems)
                      ? (out + out_elems) : gws;

    cudaFuncSetAttribute(mma_gemm<false>, cudaFuncAttributeMaxDynamicSharedMemorySize, SMEM_GEMM);
    cudaFuncSetAttribute(mma_gemm<true>,  cudaFuncAttributeMaxDynamicSharedMemorySize, SMEM_GEMM);
    cudaFuncSetAttribute(titan_scan,      cudaFuncAttributeMaxDynamicSharedMemorySize, SCAN_SMEM);

    // one-time stream/event resources (handles only; identical work per call)
    static cudaStream_t s1 = nullptr;
    static cudaEvent_t evFork = nullptr, evW = nullptr, evWo = nullptr,
                       evScan[NPART] = {}, evOut = nullptr;
    if (!s1) {
        cudaStreamCreateWithFlags(&s1, cudaStreamNonBlocking);
        cudaEventCreateWithFlags(&evFork, cudaEventDisableTiming);
        cudaEventCreateWithFlags(&evW,    cudaEventDisableTiming);
        cudaEventCreateWithFlags(&evWo,   cudaEventDisableTiming);
        for (int p = 0; p < NPART; p++)
            cudaEventCreateWithFlags(&evScan[p], cudaEventDisableTiming);
        cudaEventCreateWithFlags(&evOut, cudaEventDisableTiming);
    }

    // ---- fork ----
    cudaEventRecord(evFork, 0);
    cudaStreamWaitEvent(s1, evFork, 0);

    // ---- s1: weight prep (overlaps split_x on s0) ----
    {
        int kn = DIMV * HDV;
        transpose_split2f_kernel<<<(kn + 255) / 256, 256, 0, s1>>>(
            Wq, wqkvh + 0 * HDV * DIMV, wqkvl + 0 * HDV * DIMV, DIMV, HDV);
        transpose_split2f_kernel<<<(kn + 255) / 256, 256, 0, s1>>>(
            Wk, wqkvh + 1 * HDV * DIMV, wqkvl + 1 * HDV * DIMV, DIMV, HDV);
        transpose_split2f_kernel<<<(kn + 255) / 256, 256, 0, s1>>>(
            Wv, wqkvh + 2 * HDV * DIMV, wqkvl + 2 * HDV * DIMV, DIMV, HDV);
        concat_bias_kernel<<<1, 128, 0, s1>>>(bq, bk, bv, bqkv);
        cudaEventRecord(evW, s1);
        transpose_split2b_kernel<<<(kn + 255) / 256, 256, 0, s1>>>(Wo, woh, wol, HDV, DIMV);
        cudaEventRecord(evWo, s1);
    }

    // ---- s0: split x, QKV GEMM, gram, scan parts ----
    {
        int n4 = MTOK * DIMV / 4;
        split2f_kernel<<<(n4 + 255) / 256, 256>>>(x, xh, xl, n4);
    }
    cudaStreamWaitEvent(0, evW, 0);
    mma_gemm<false><<<dim3(MTOK / 128, NQKV / 128), 256, SMEM_GEMM>>>(
        xh, xl, wqkvh, wqkvl, bqkv, gqkv, NQKV, DIMV, -1);
    gram_kernel<<<BB * NCHUNK, 256>>>(gqkv, gG);

    for (int p = 0; p < NPART; p++) {
        const float* wsrc = (p == 0) ? state : wfin;
        titan_scan<<<128, 256, SCAN_SMEM>>>(gqkv, gG, wsrc, lr, yh, yl, wfin, p * PCH);
        cudaEventRecord(evScan[p], 0);
    }

    // ---- s1: out-GEMM token-parts (overlap with later scan parts) ----
    cudaStreamWaitEvent(s1, evWo, 0);
    for (int p = 0; p < NPART; p++) {
        cudaStreamWaitEvent(s1, evScan[p], 0);
        // part p covers tokens [p*512, p*512+512) of every batch: grid (32, 16)
        mma_gemm<true><<<dim3(32, DIMV / 128), 256, SMEM_GEMM, s1>>>(
            yh, yl, woh, wol, bo, out, DIMV, HDV, p * (PCH * SCAN_CH));
    }
    cudaEventRecord(evOut, s1);
    cudaStreamWaitEvent(0, evOut, 0);
}

// round 12
// speedup vs baseline: 1.0253x; 1.0253x over previous
#include <cuda_runtime.h>
#include <cuda_fp16.h>
#include <cuda_bf16.h>
#include <cstdint>

#define BB   8
#define SS   2048
#define DIMV 2048
#define HDV  128
#define MTOK (BB*SS)        // 16384 tokens
#define NQKV 384            // q|k|v concat width
#define SPLIT_SCALE 2048.0f
#define INV_SPLIT   4.8828125e-4f   // 1/2048
#define SCAN_CH 16                   // scan chunk (steps)
#define NCHUNK (SS / SCAN_CH)        // 128

// ---------------------------------------------------------------------------
// Scratch (device globals; no allocation allowed)
// ---------------------------------------------------------------------------
__device__ __half g_xh[MTOK * DIMV];
__device__ __half g_xl[MTOK * DIMV];
__device__ __half g_wqkvh[NQKV * DIMV];   // [384][2048] K-major
__device__ __half g_wqkvl[NQKV * DIMV];
__device__ __nv_bfloat16 g_woh[DIMV * HDV];  // [2048][128] K-major
__device__ __nv_bfloat16 g_wol[DIMV * HDV];
__device__ float g_bqkv[NQKV];
__device__ float g_qkv[MTOK * NQKV];      // [token][384] = q|k|v
__device__ __nv_bfloat16 g_yh[MTOK * HDV], g_yl[MTOK * HDV];
__device__ float g_wfin_scratch[BB * HDV * HDV];
__device__ float g_G[BB * NCHUNK * 512];  // per chunk: [256]=Gkk, [256]=Gqk

// ---------------------------------------------------------------------------
// Helpers
// ---------------------------------------------------------------------------
__device__ __forceinline__ uint32_t smem_to_u32(const void* p) {
    uint32_t a;
    asm("{ .reg .u64 t; cvta.to.shared.u64 t, %1; cvt.u32.u64 %0, t; }"
        : "=r"(a) : "l"(p));
    return a;
}

#define SMEM_SWIZZLE_128B(off) ((off) ^ (((off) >> 3) & 0x70))

#define CP_ASYNC_CG(dst, src) \
    asm volatile("cp.async.cg.shared.global [%0], [%1], 16;" \
        :: "r"(dst), "l"(src) : "memory")
#define CP_COMMIT() asm volatile("cp.async.commit_group;" ::: "memory")
#define CP_WAIT_1() asm volatile("cp.async.wait_group 1;" ::: "memory")
#define CP_WAIT_0() asm volatile("cp.async.wait_group 0;" ::: "memory")

__device__ __forceinline__ void ldsm_x4(uint32_t (&r)[4], uint32_t addr) {
    asm volatile("ldmatrix.sync.aligned.m8n8.x4.shared.b16 {%0,%1,%2,%3}, [%4];"
        : "=r"(r[0]), "=r"(r[1]), "=r"(r[2]), "=r"(r[3]) : "r"(addr));
}

template <bool BF16>
__device__ __forceinline__ void mma_16(float (&c)[4], const uint32_t (&a)[4],
                                       const uint32_t b0, const uint32_t b1) {
    if (BF16)
        asm volatile("mma.sync.aligned.m16n8k16.row.col.f32.bf16.bf16.f32 "
            "{%0,%1,%2,%3}, {%4,%5,%6,%7}, {%8,%9}, {%0,%1,%2,%3};"
            : "+f"(c[0]), "+f"(c[1]), "+f"(c[2]), "+f"(c[3])
            : "r"(a[0]), "r"(a[1]), "r"(a[2]), "r"(a[3]), "r"(b0), "r"(b1));
    else
        asm volatile("mma.sync.aligned.m16n8k16.row.col.f32.f16.f16.f32 "
            "{%0,%1,%2,%3}, {%4,%5,%6,%7}, {%8,%9}, {%0,%1,%2,%3};"
            : "+f"(c[0]), "+f"(c[1]), "+f"(c[2]), "+f"(c[3])
            : "r"(a[0]), "r"(a[1]), "r"(a[2]), "r"(a[3]), "r"(b0), "r"(b1));
}

// ---------------------------------------------------------------------------
// splits
// ---------------------------------------------------------------------------
__device__ __forceinline__ void split2f(float x, unsigned short& h, unsigned short& l) {
    __half hh = __float2half_rn(x);
    float r = (x - __half2float(hh)) * SPLIT_SCALE;
    h = __half_as_ushort(hh);
    l = __half_as_ushort(__float2half_rn(r));
}
__device__ __forceinline__ void split2b(float x, unsigned short& h, unsigned short& l) {
    __nv_bfloat16 hh = __float2bfloat16(x);
    float r = x - __bfloat162float(hh);
    h = __bfloat16_as_ushort(hh);
    l = __bfloat16_as_ushort(__float2bfloat16(r));
}

__global__ __launch_bounds__(256) void split2f_kernel(
    const float* __restrict__ in, __half* __restrict__ h,
    __half* __restrict__ l, int n4)
{
    int i = blockIdx.x * 256 + threadIdx.x;
    if (i >= n4) return;
    float4 x = reinterpret_cast<const float4*>(in)[i];
    ushort4 H, L;
    split2f(x.x, H.x, L.x); split2f(x.y, H.y, L.y);
    split2f(x.z, H.z, L.z); split2f(x.w, H.w, L.w);
    reinterpret_cast<ushort4*>(h)[i] = H;
    reinterpret_cast<ushort4*>(l)[i] = L;
}

__global__ __launch_bounds__(256) void transpose_split2f_kernel(
    const float* __restrict__ in, __half* __restrict__ h,
    __half* __restrict__ l, int K, int N)
{
    int idx = blockIdx.x * 256 + threadIdx.x;
    if (idx >= K * N) return;
    int k = idx / N, n = idx - k * N;
    unsigned short H, L;
    split2f(in[idx], H, L);
    size_t o = (size_t)n * K + k;
    h[o] = __ushort_as_half(H);
    l[o] = __ushort_as_half(L);
}

__global__ __launch_bounds__(256) void transpose_split2b_kernel(
    const float* __restrict__ in, __nv_bfloat16* __restrict__ h,
    __nv_bfloat16* __restrict__ l, int K, int N)
{
    int idx = blockIdx.x * 256 + threadIdx.x;
    if (idx >= K * N) return;
    int k = idx / N, n = idx - k * N;
    unsigned short H, L;
    split2b(in[idx], H, L);
    size_t o = (size_t)n * K + k;
    h[o] = __ushort_as_bfloat16(H);
    l[o] = __ushort_as_bfloat16(L);
}

__global__ void concat_bias_kernel(const float* __restrict__ a,
                                   const float* __restrict__ b,
                                   const float* __restrict__ c,
                                   float* __restrict__ o)
{
    int t = threadIdx.x;
    if (t < HDV) { o[t] = a[t]; o[HDV + t] = b[t]; o[2 * HDV + t] = c[t]; }
}

// ---------------------------------------------------------------------------
// HMMA GEMM, 2-way split operands (R9, unchanged)
// ---------------------------------------------------------------------------
#define TILE_B   16384
#define STAGE_B  (4 * TILE_B)
#define SMEM_GEMM (2 * STAGE_B)

template <bool BF16>
__global__ __launch_bounds__(256) void mma_gemm(
    const void* __restrict__ A0v, const void* __restrict__ A1v,
    const void* __restrict__ B0v, const void* __restrict__ B1v,
    const float* __restrict__ bias, float* __restrict__ O,
    int N, int K)
{
    const float mergeScale = BF16 ? 1.0f : INV_SPLIT;
    extern __shared__ char smem[];
    const uint32_t sbase = smem_to_u32(smem);
    const int tid = threadIdx.x;
    const int lane = tid & 31, wid = tid >> 5;
    const int warp_m = wid & 3;
    const int warp_n = wid >> 2;
    const int m0 = blockIdx.x * 128, n0 = blockIdx.y * 128;
    const int NC = K >> 6;

    const uint16_t* src[4] = {
        (const uint16_t*)A0v + (size_t)m0 * K, (const uint16_t*)A1v + (size_t)m0 * K,
        (const uint16_t*)B0v + (size_t)n0 * K, (const uint16_t*)B1v + (size_t)n0 * K };

    const int lrow = tid >> 1;
    const int lhalf = tid & 1;

    float master[2][8][4];
#pragma unroll
    for (int a = 0; a < 2; a++)
#pragma unroll
        for (int b = 0; b < 8; b++)
#pragma unroll
            for (int c = 0; c < 4; c++) master[a][b][c] = 0.0f;

    auto load_stage = [&](int buf, int chunk) {
        const int kc = chunk << 6;
        const uint32_t sb = sbase + buf * STAGE_B;
#pragma unroll
        for (int t = 0; t < 4; t++) {
            const char* g = (const char*)(src[t] + (size_t)lrow * K + kc) + lhalf * 64;
            const uint32_t tb = sb + t * TILE_B;
#pragma unroll
            for (int i = 0; i < 4; i++) {
                uint32_t off = (uint32_t)(lrow * 128 + lhalf * 64 + i * 16);
                CP_ASYNC_CG(tb + SMEM_SWIZZLE_128B(off), g + i * 16);
            }
        }
    };

    load_stage(0, 0);
    CP_COMMIT();

    float chunk[2][8][4];

    for (int c = 0; c < NC; c++) {
        const int s = c & 1;
        if (c + 1 < NC) { load_stage(s ^ 1, c + 1); CP_COMMIT(); CP_WAIT_1(); }
        else            { CP_WAIT_0(); }
        __syncthreads();

        const uint32_t base = sbase + s * STAGE_B;

        // ---- pass A: mixed products (h*l + l*h) ----
#pragma unroll
        for (int a = 0; a < 2; a++)
#pragma unroll
            for (int b = 0; b < 8; b++)
#pragma unroll
                for (int cc = 0; cc < 4; cc++) chunk[a][b][cc] = 0.0f;

#pragma unroll
        for (int kk = 0; kk < 4; kk++) {
            uint32_t ah[2][4], al[2][4];
#pragma unroll
            for (int mt = 0; mt < 2; mt++) {
                int row = warp_m * 32 + mt * 16 + (lane & 15);
                int col = kk * 32 + ((lane >> 4) << 4);
                uint32_t off = SMEM_SWIZZLE_128B((uint32_t)(row * 128 + col));
                ldsm_x4(ah[mt], base + off);
                ldsm_x4(al[mt], base + TILE_B + off);
            }
#pragma unroll
            for (int p = 0; p < 4; p++) {
                int row = warp_n * 64 + p * 16 + (lane & 7) + (((lane >> 4) & 1) << 3);
                int col = kk * 32 + (((lane >> 3) & 1) << 4);
                uint32_t off = SMEM_SWIZZLE_128B((uint32_t)(row * 128 + col));
                uint32_t bh[4], bl[4];
                ldsm_x4(bh, base + 2 * TILE_B + off);
                ldsm_x4(bl, base + 3 * TILE_B + off);
#pragma unroll
                for (int mt = 0; mt < 2; mt++)
#pragma unroll
                    for (int n2 = 0; n2 < 2; n2++) {
                        mma_16<BF16>(chunk[mt][2 * p + n2], ah[mt], bl[2 * n2], bl[2 * n2 + 1]);
                        mma_16<BF16>(chunk[mt][2 * p + n2], al[mt], bh[2 * n2], bh[2 * n2 + 1]);
                    }
            }
        }
#pragma unroll
        for (int a = 0; a < 2; a++)
#pragma unroll
            for (int b = 0; b < 8; b++)
#pragma unroll
                for (int cc = 0; cc < 4; cc++)
                    master[a][b][cc] = fmaf(chunk[a][b][cc], mergeScale, master[a][b][cc]);

        // ---- pass B: h*h ----
#pragma unroll
        for (int a = 0; a < 2; a++)
#pragma unroll
            for (int b = 0; b < 8; b++)
#pragma unroll
                for (int cc = 0; cc < 4; cc++) chunk[a][b][cc] = 0.0f;

#pragma unroll
        for (int kk = 0; kk < 4; kk++) {
            uint32_t ah[2][4];
#pragma unroll
            for (int mt = 0; mt < 2; mt++) {
                int row = warp_m * 32 + mt * 16 + (lane & 15);
                int col = kk * 32 + ((lane >> 4) << 4);
                uint32_t off = SMEM_SWIZZLE_128B((uint32_t)(row * 128 + col));
                ldsm_x4(ah[mt], base + off);
            }
#pragma unroll
            for (int p = 0; p < 4; p++) {
                int row = warp_n * 64 + p * 16 + (lane & 7) + (((lane >> 4) & 1) << 3);
                int col = kk * 32 + (((lane >> 3) & 1) << 4);
                uint32_t off = SMEM_SWIZZLE_128B((uint32_t)(row * 128 + col));
                uint32_t bh[4];
                ldsm_x4(bh, base + 2 * TILE_B + off);
#pragma unroll
                for (int mt = 0; mt < 2; mt++)
#pragma unroll
                    for (int n2 = 0; n2 < 2; n2++)
                        mma_16<BF16>(chunk[mt][2 * p + n2], ah[mt], bh[2 * n2], bh[2 * n2 + 1]);
            }
        }
#pragma unroll
        for (int a = 0; a < 2; a++)
#pragma unroll
            for (int b = 0; b < 8; b++)
#pragma unroll
                for (int cc = 0; cc < 4; cc++) master[a][b][cc] += chunk[a][b][cc];

        __syncthreads();
    }

    // ---- epilogue ----
    float2 bcol[8];
#pragma unroll
    for (int nt = 0; nt < 8; nt++) {
        int cbase = n0 + warp_n * 64 + nt * 8 + (lane & 3) * 2;
        bcol[nt].x = __ldg(bias + cbase);
        bcol[nt].y = __ldg(bias + cbase + 1);
    }
#pragma unroll
    for (int mt = 0; mt < 2; mt++) {
        int r0 = m0 + warp_m * 32 + mt * 16 + (lane >> 2);
#pragma unroll
        for (int nt = 0; nt < 8; nt++) {
            int cbase = n0 + warp_n * 64 + nt * 8 + (lane & 3) * 2;
            float2 v0 = { master[mt][nt][0] + bcol[nt].x, master[mt][nt][1] + bcol[nt].y };
            float2 v1 = { master[mt][nt][2] + bcol[nt].x, master[mt][nt][3] + bcol[nt].y };
            *reinterpret_cast<float2*>(O + (size_t)r0 * N + cbase) = v0;
            *reinterpret_cast<float2*>(O + (size_t)(r0 + 8) * N + cbase) = v1;
        }
    }
}

// ---------------------------------------------------------------------------
// Gram kernel (R9): Gkk[u][t]=k_u.k_t, Gqk[u][t]=k_u.q_t per (batch, chunk).
// ---------------------------------------------------------------------------
__global__ __launch_bounds__(256) void gram_kernel(
    const float* __restrict__ qkv, float* __restrict__ G)
{
    const int blk = blockIdx.x;               // b*NCHUNK + c
    const int b = blk >> 7, c = blk & (NCHUNK - 1);
    const int u = threadIdx.x >> 4, t = threadIdx.x & 15;
    const float* basep = qkv + ((size_t)b * SS + c * SCAN_CH) * NQKV;
    const float4* ku = (const float4*)(basep + u * NQKV + 128);
    const float4* kt = (const float4*)(basep + t * NQKV + 128);
    const float4* qt = (const float4*)(basep + t * NQKV);
    float skk = 0.0f, sqk = 0.0f;
#pragma unroll 8
    for (int j = 0; j < 32; j++) {
        float4 a = __ldg(ku + j), bk = __ldg(kt + j), bq = __ldg(qt + j);
        skk += a.x * bk.x + a.y * bk.y + a.z * bk.z + a.w * bk.w;
        sqk += a.x * bq.x + a.y * bq.y + a.z * bq.z + a.w * bq.w;
    }
    float* go = G + (size_t)blk * 512;
    go[u * 16 + t] = skk;
    go[256 + u * 16 + t] = sqk;
}

// ---------------------------------------------------------------------------
// Chunked delta-rule scan (R9 math), single launch; y written directly as
// bf16 2-way split (exact h+l), removing the separate split pass.
// ---------------------------------------------------------------------------
#define QKV_F   (SCAN_CH * NQKV)             // 6144 floats
#define STAGE_F (QKV_F + 512)
#define SCAN_SMEM (2 * STAGE_F * 4)          // 53248 bytes

__global__ __launch_bounds__(256) void titan_scan(
    const float* __restrict__ qkv, const float* __restrict__ G,
    const float* __restrict__ state, const float* __restrict__ lr_ptr,
    __nv_bfloat16* __restrict__ yh, __nv_bfloat16* __restrict__ yl,
    float* __restrict__ wfin)
{
    extern __shared__ float smemf[];
    const int tid  = threadIdx.x;
    const int warp = tid >> 5;
    const int lane = tid & 31;
    const int b    = blockIdx.x >> 4;
    const int i    = ((blockIdx.x & 15) << 3) + warp;

    const float lr = *lr_ptr;
    const float* base  = qkv + (size_t)b * SS * NQKV;
    const float* gbase = G + (size_t)b * NCHUNK * 512;
    __nv_bfloat16* yhb = yh + (size_t)b * SS * HDV + i;
    __nv_bfloat16* ylb = yl + (size_t)b * SS * HDV + i;

    const uint32_t s0 = smem_to_u32(smemf);
    auto stage = [&](int c) {
        if (c < NCHUNK) {
            const char* g = (const char*)(base + (size_t)c * QKV_F);
            const uint32_t sb = s0 + (uint32_t)(c & 1) * (STAGE_F * 4);
#pragma unroll
            for (int it = 0; it < 6; it++) {
                int idx = tid + it * 256;
                CP_ASYNC_CG(sb + idx * 16, g + idx * 16);
            }
            if (tid < 128)
                CP_ASYNC_CG(sb + QKV_F * 4 + tid * 16,
                            (const char*)(gbase + (size_t)c * 512) + tid * 16);
        }
    };
    stage(0); CP_COMMIT();
    stage(1); CP_COMMIT();

    float4 w4 = *reinterpret_cast<const float4*>(
        state + ((size_t)b * HDV + i) * HDV + lane * 4);

    for (int c = 0; c < NCHUNK; c++) {
        CP_WAIT_1();
        __syncthreads();
        const float* sb  = smemf + (c & 1) * STAGE_F;
        const float* gkk = sb + QKV_F;
        const float* gqk = gkk + 256;

        float Bv[SCAN_CH], e[SCAN_CH];
        float Asel = 0.0f;

        // ---- P1: parallel W0 dots ----
#pragma unroll
        for (int t = 0; t < SCAN_CH; t++) {
            const float* row = sb + t * NQKV;
            float4 q = *reinterpret_cast<const float4*>(row + lane * 4);
            float4 k = *reinterpret_cast<const float4*>(row + 128 + lane * 4);
            float a  = w4.x * q.x + w4.y * q.y + w4.z * q.z + w4.w * q.w;
            float bb = w4.x * k.x + w4.y * k.y + w4.z * k.z + w4.w * k.w;
#pragma unroll
            for (int o = 16; o > 0; o >>= 1) {
                a  += __shfl_xor_sync(0xffffffffu, a,  o);
                bb += __shfl_xor_sync(0xffffffffu, bb, o);
            }
            Bv[t] = bb;
            if (lane == t) Asel = a;
        }

        // ---- P2: serial triangular recursion (all lanes redundant) ----
#pragma unroll
        for (int t = 0; t < SCAN_CH; t++) {
            float acc = Bv[t];
#pragma unroll
            for (int u = 0; u < SCAN_CH; u++)
                if (u < t) acc = fmaf(-e[u], gkk[u * 16 + t], acc);
            e[t] = lr * (acc - sb[t * NQKV + 256 + i]);
        }

        // ---- P3a: outputs, fused bf16 split ----
        if (lane < SCAN_CH) {
            float dq = Asel;
#pragma unroll
            for (int u = 0; u < SCAN_CH - 1; u++)
                if (u < lane) dq = fmaf(-e[u], gqk[u * 16 + lane], dq);
            unsigned short H, L;
            split2b(dq, H, L);
            size_t off = (size_t)(c * SCAN_CH + lane) * HDV;
            yhb[off] = __ushort_as_bfloat16(H);
            ylb[off] = __ushort_as_bfloat16(L);
        }

        // ---- P3b: W update ----
#pragma unroll
        for (int u = 0; u < SCAN_CH; u++) {
            float4 k = *reinterpret_cast<const float4*>(sb + u * NQKV + 128 + lane * 4);
            w4.x = fmaf(-e[u], k.x, w4.x);
            w4.y = fmaf(-e[u], k.y, w4.y);
            w4.z = fmaf(-e[u], k.z, w4.z);
            w4.w = fmaf(-e[u], k.w, w4.w);
        }

        __syncthreads();
        stage(c + 2); CP_COMMIT();
    }

    *reinterpret_cast<float4*>(wfin + ((size_t)b * HDV + i) * HDV + lane * 4) = w4;
}

// ---------------------------------------------------------------------------
// Launch: weight prep on a side stream overlapping the x-split; everything
// else sequential on the main stream (scan runs alone — no contention).
// ---------------------------------------------------------------------------
extern "C" void kernel_launch(void* const* d_in, const int* in_sizes, int n_in,
                              void* d_out, int out_size)
{
    const float* x     = (const float*)d_in[0];
    const float* state = (const float*)d_in[1];
    const float* Wq    = (const float*)d_in[2];
    const float* bq    = (const float*)d_in[3];
    const float* Wk    = (const float*)d_in[4];
    const float* bk    = (const float*)d_in[5];
    const float* Wv    = (const float*)d_in[6];
    const float* bv    = (const float*)d_in[7];
    const float* Wo    = (const float*)d_in[8];
    const float* bo    = (const float*)d_in[9];
    const float* lr    = (const float*)d_in[10];
    float* out = (float*)d_out;

    __half *xh, *xl, *wqkvh, *wqkvl;
    __nv_bfloat16 *yh, *yl, *woh, *wol;
    float *bqkv, *gqkv, *gws, *gG;
    cudaGetSymbolAddress((void**)&xh, g_xh);
    cudaGetSymbolAddress((void**)&xl, g_xl);
    cudaGetSymbolAddress((void**)&yh, g_yh);
    cudaGetSymbolAddress((void**)&yl, g_yl);
    cudaGetSymbolAddress((void**)&wqkvh, g_wqkvh);
    cudaGetSymbolAddress((void**)&wqkvl, g_wqkvl);
    cudaGetSymbolAddress((void**)&woh, g_woh);
    cudaGetSymbolAddress((void**)&wol, g_wol);
    cudaGetSymbolAddress((void**)&bqkv, g_bqkv);
    cudaGetSymbolAddress((void**)&gqkv, g_qkv);
    cudaGetSymbolAddress((void**)&gws, g_wfin_scratch);
    cudaGetSymbolAddress((void**)&gG, g_G);

    const size_t out_elems  = (size_t)BB * SS * DIMV;
    const size_t wfin_elems = (size_t)BB * HDV * HDV;
    float* wfin = ((size_t)out_size >= out_elems + wfin_elems)
                      ? (out + out_elems) : gws;

    cudaFuncSetAttribute(mma_gemm<false>, cudaFuncAttributeMaxDynamicSharedMemorySize, SMEM_GEMM);
    cudaFuncSetAttribute(mma_gemm<true>,  cudaFuncAttributeMaxDynamicSharedMemorySize, SMEM_GEMM);
    cudaFuncSetAttribute(titan_scan,      cudaFuncAttributeMaxDynamicSharedMemorySize, SCAN_SMEM);

    // one-time stream/event handles (resources only; identical work per call)
    static cudaStream_t s1 = nullptr;
    static cudaEvent_t evFork = nullptr, evW = nullptr, evWo = nullptr;
    if (!s1) {
        cudaStreamCreateWithFlags(&s1, cudaStreamNonBlocking);
        cudaEventCreateWithFlags(&evFork, cudaEventDisableTiming);
        cudaEventCreateWithFlags(&evW,    cudaEventDisableTiming);
        cudaEventCreateWithFlags(&evWo,   cudaEventDisableTiming);
    }

    // ---- fork ----
    cudaEventRecord(evFork, 0);
    cudaStreamWaitEvent(s1, evFork, 0);

    // ---- s1: weight prep (overlaps split_x on the main stream) ----
    {
        int kn = DIMV * HDV;
        transpose_split2f_kernel<<<(kn + 255) / 256, 256, 0, s1>>>(
            Wq, wqkvh + 0 * HDV * DIMV, wqkvl + 0 * HDV * DIMV, DIMV, HDV);
        transpose_split2f_kernel<<<(kn + 255) / 256, 256, 0, s1>>>(
            Wk, wqkvh + 1 * HDV * DIMV, wqkvl + 1 * HDV * DIMV, DIMV, HDV);
        transpose_split2f_kernel<<<(kn + 255) / 256, 256, 0, s1>>>(
            Wv, wqkvh + 2 * HDV * DIMV, wqkvl + 2 * HDV * DIMV, DIMV, HDV);
        concat_bias_kernel<<<1, 128, 0, s1>>>(bq, bk, bv, bqkv);
        cudaEventRecord(evW, s1);
        transpose_split2b_kernel<<<(kn + 255) / 256, 256, 0, s1>>>(Wo, woh, wol, HDV, DIMV);
        cudaEventRecord(evWo, s1);
    }

    // ---- main: split x -> QKV GEMM -> gram -> scan -> out GEMM ----
    {
        int n4 = MTOK * DIMV / 4;
        split2f_kernel<<<(n4 + 255) / 256, 256>>>(x, xh, xl, n4);
    }
    cudaStreamWaitEvent(0, evW, 0);
    mma_gemm<false><<<dim3(MTOK / 128, NQKV / 128), 256, SMEM_GEMM>>>(
        xh, xl, wqkvh, wqkvl, bqkv, gqkv, NQKV, DIMV);
    gram_kernel<<<BB * NCHUNK, 256>>>(gqkv, gG);
    titan_scan<<<128, 256, SCAN_SMEM>>>(gqkv, gG, state, lr, yh, yl, wfin);

    cudaStreamWaitEvent(0, evWo, 0);
    mma_gemm<true><<<dim3(MTOK / 128, DIMV / 128), 256, SMEM_GEMM>>>(
        yh, yl, woh, wol, bo, out, DIMV, HDV);
}

// round 13
// speedup vs baseline: 1.0517x; 1.0257x over previous
#include <cuda_runtime.h>
#include <cuda_fp16.h>
#include <cuda_bf16.h>
#include <cstdint>

#define BB   8
#define SS   2048
#define DIMV 2048
#define HDV  128
#define MTOK (BB*SS)        // 16384 tokens
#define NQKV 384            // q|k|v concat width
#define SPLIT_SCALE 2048.0f
#define INV_SPLIT   4.8828125e-4f   // 1/2048
#define SCAN_CH 16                   // scan chunk (steps)
#define NCHUNK (SS / SCAN_CH)        // 128

// ---------------------------------------------------------------------------
// Scratch (device globals; no allocation allowed)
// ---------------------------------------------------------------------------
__device__ __half g_xh[MTOK * DIMV];
__device__ __half g_xl[MTOK * DIMV];
__device__ __half g_wqkvh[NQKV * DIMV];   // [384][2048] K-major
__device__ __half g_wqkvl[NQKV * DIMV];
__device__ __nv_bfloat16 g_woh[DIMV * HDV];  // [2048][128] K-major
__device__ __nv_bfloat16 g_wol[DIMV * HDV];
__device__ float g_bqkv[NQKV];
__device__ float g_qkv[MTOK * NQKV];      // [token][384] = q|k|v
__device__ float g_y[MTOK * HDV];
__device__ __nv_bfloat16 g_yh[MTOK * HDV], g_yl[MTOK * HDV];
__device__ float g_wfin_scratch[BB * HDV * HDV];
__device__ float g_G[BB * NCHUNK * 512];  // per chunk: [256]=Gkk, [256]=Gqk

// ---------------------------------------------------------------------------
// Helpers
// ---------------------------------------------------------------------------
__device__ __forceinline__ uint32_t smem_to_u32(const void* p) {
    uint32_t a;
    asm("{ .reg .u64 t; cvta.to.shared.u64 t, %1; cvt.u32.u64 %0, t; }"
        : "=r"(a) : "l"(p));
    return a;
}

#define SMEM_SWIZZLE_128B(off) ((off) ^ (((off) >> 3) & 0x70))

#define CP_ASYNC_CG(dst, src) \
    asm volatile("cp.async.cg.shared.global [%0], [%1], 16;" \
        :: "r"(dst), "l"(src) : "memory")
#define CP_COMMIT() asm volatile("cp.async.commit_group;" ::: "memory")
#define CP_WAIT_1() asm volatile("cp.async.wait_group 1;" ::: "memory")
#define CP_WAIT_0() asm volatile("cp.async.wait_group 0;" ::: "memory")

__device__ __forceinline__ void ldsm_x4(uint32_t (&r)[4], uint32_t addr) {
    asm volatile("ldmatrix.sync.aligned.m8n8.x4.shared.b16 {%0,%1,%2,%3}, [%4];"
        : "=r"(r[0]), "=r"(r[1]), "=r"(r[2]), "=r"(r[3]) : "r"(addr));
}

template <bool BF16>
__device__ __forceinline__ void mma_16(float (&c)[4], const uint32_t (&a)[4],
                                       const uint32_t b0, const uint32_t b1) {
    if (BF16)
        asm volatile("mma.sync.aligned.m16n8k16.row.col.f32.bf16.bf16.f32 "
            "{%0,%1,%2,%3}, {%4,%5,%6,%7}, {%8,%9}, {%0,%1,%2,%3};"
            : "+f"(c[0]), "+f"(c[1]), "+f"(c[2]), "+f"(c[3])
            : "r"(a[0]), "r"(a[1]), "r"(a[2]), "r"(a[3]), "r"(b0), "r"(b1));
    else
        asm volatile("mma.sync.aligned.m16n8k16.row.col.f32.f16.f16.f32 "
            "{%0,%1,%2,%3}, {%4,%5,%6,%7}, {%8,%9}, {%0,%1,%2,%3};"
            : "+f"(c[0]), "+f"(c[1]), "+f"(c[2]), "+f"(c[3])
            : "r"(a[0]), "r"(a[1]), "r"(a[2]), "r"(a[3]), "r"(b0), "r"(b1));
}

// ---------------------------------------------------------------------------
// splits
// ---------------------------------------------------------------------------
__device__ __forceinline__ void split2f(float x, unsigned short& h, unsigned short& l) {
    __half hh = __float2half_rn(x);
    float r = (x - __half2float(hh)) * SPLIT_SCALE;
    h = __half_as_ushort(hh);
    l = __half_as_ushort(__float2half_rn(r));
}
__device__ __forceinline__ void split2b(float x, unsigned short& h, unsigned short& l) {
    __nv_bfloat16 hh = __float2bfloat16(x);
    float r = x - __bfloat162float(hh);
    h = __bfloat16_as_ushort(hh);
    l = __bfloat16_as_ushort(__float2bfloat16(r));
}

__global__ __launch_bounds__(256) void split2f_kernel(
    const float* __restrict__ in, __half* __restrict__ h,
    __half* __restrict__ l, int n4)
{
    int i = blockIdx.x * 256 + threadIdx.x;
    if (i >= n4) return;
    float4 x = reinterpret_cast<const float4*>(in)[i];
    ushort4 H, L;
    split2f(x.x, H.x, L.x); split2f(x.y, H.y, L.y);
    split2f(x.z, H.z, L.z); split2f(x.w, H.w, L.w);
    reinterpret_cast<ushort4*>(h)[i] = H;
    reinterpret_cast<ushort4*>(l)[i] = L;
}

__global__ __launch_bounds__(256) void split2b_kernel(
    const float* __restrict__ in, __nv_bfloat16* __restrict__ h,
    __nv_bfloat16* __restrict__ l, int n4)
{
    int i = blockIdx.x * 256 + threadIdx.x;
    if (i >= n4) return;
    float4 x = reinterpret_cast<const float4*>(in)[i];
    ushort4 H, L;
    split2b(x.x, H.x, L.x); split2b(x.y, H.y, L.y);
    split2b(x.z, H.z, L.z); split2b(x.w, H.w, L.w);
    reinterpret_cast<ushort4*>(h)[i] = H;
    reinterpret_cast<ushort4*>(l)[i] = L;
}

__global__ __launch_bounds__(256) void transpose_split2f_kernel(
    const float* __restrict__ in, __half* __restrict__ h,
    __half* __restrict__ l, int K, int N)
{
    int idx = blockIdx.x * 256 + threadIdx.x;
    if (idx >= K * N) return;
    int k = idx / N, n = idx - k * N;
    unsigned short H, L;
    split2f(in[idx], H, L);
    size_t o = (size_t)n * K + k;
    h[o] = __ushort_as_half(H);
    l[o] = __ushort_as_half(L);
}

__global__ __launch_bounds__(256) void transpose_split2b_kernel(
    const float* __restrict__ in, __nv_bfloat16* __restrict__ h,
    __nv_bfloat16* __restrict__ l, int K, int N)
{
    int idx = blockIdx.x * 256 + threadIdx.x;
    if (idx >= K * N) return;
    int k = idx / N, n = idx - k * N;
    unsigned short H, L;
    split2b(in[idx], H, L);
    size_t o = (size_t)n * K + k;
    h[o] = __ushort_as_bfloat16(H);
    l[o] = __ushort_as_bfloat16(L);
}

__global__ void concat_bias_kernel(const float* __restrict__ a,
                                   const float* __restrict__ b,
                                   const float* __restrict__ c,
                                   float* __restrict__ o)
{
    int t = threadIdx.x;
    if (t < HDV) { o[t] = a[t]; o[HDV + t] = b[t]; o[2 * HDV + t] = c[t]; }
}

// ---------------------------------------------------------------------------
// HMMA GEMM, 2-way split operands (R9, unchanged)
// ---------------------------------------------------------------------------
#define TILE_B   16384
#define STAGE_B  (4 * TILE_B)
#define SMEM_GEMM (2 * STAGE_B)

template <bool BF16>
__global__ __launch_bounds__(256) void mma_gemm(
    const void* __restrict__ A0v, const void* __restrict__ A1v,
    const void* __restrict__ B0v, const void* __restrict__ B1v,
    const float* __restrict__ bias, float* __restrict__ O,
    int N, int K)
{
    const float mergeScale = BF16 ? 1.0f : INV_SPLIT;
    extern __shared__ char smem[];
    const uint32_t sbase = smem_to_u32(smem);
    const int tid = threadIdx.x;
    const int lane = tid & 31, wid = tid >> 5;
    const int warp_m = wid & 3;
    const int warp_n = wid >> 2;
    const int m0 = blockIdx.x * 128, n0 = blockIdx.y * 128;
    const int NC = K >> 6;

    const uint16_t* src[4] = {
        (const uint16_t*)A0v + (size_t)m0 * K, (const uint16_t*)A1v + (size_t)m0 * K,
        (const uint16_t*)B0v + (size_t)n0 * K, (const uint16_t*)B1v + (size_t)n0 * K };

    const int lrow = tid >> 1;
    const int lhalf = tid & 1;

    float master[2][8][4];
#pragma unroll
    for (int a = 0; a < 2; a++)
#pragma unroll
        for (int b = 0; b < 8; b++)
#pragma unroll
            for (int c = 0; c < 4; c++) master[a][b][c] = 0.0f;

    auto load_stage = [&](int buf, int chunk) {
        const int kc = chunk << 6;
        const uint32_t sb = sbase + buf * STAGE_B;
#pragma unroll
        for (int t = 0; t < 4; t++) {
            const char* g = (const char*)(src[t] + (size_t)lrow * K + kc) + lhalf * 64;
            const uint32_t tb = sb + t * TILE_B;
#pragma unroll
            for (int i = 0; i < 4; i++) {
                uint32_t off = (uint32_t)(lrow * 128 + lhalf * 64 + i * 16);
                CP_ASYNC_CG(tb + SMEM_SWIZZLE_128B(off), g + i * 16);
            }
        }
    };

    load_stage(0, 0);
    CP_COMMIT();

    float chunk[2][8][4];

    for (int c = 0; c < NC; c++) {
        const int s = c & 1;
        if (c + 1 < NC) { load_stage(s ^ 1, c + 1); CP_COMMIT(); CP_WAIT_1(); }
        else            { CP_WAIT_0(); }
        __syncthreads();

        const uint32_t base = sbase + s * STAGE_B;

        // ---- pass A: mixed products (h*l + l*h) ----
#pragma unroll
        for (int a = 0; a < 2; a++)
#pragma unroll
            for (int b = 0; b < 8; b++)
#pragma unroll
                for (int cc = 0; cc < 4; cc++) chunk[a][b][cc] = 0.0f;

#pragma unroll
        for (int kk = 0; kk < 4; kk++) {
            uint32_t ah[2][4], al[2][4];
#pragma unroll
            for (int mt = 0; mt < 2; mt++) {
                int row = warp_m * 32 + mt * 16 + (lane & 15);
                int col = kk * 32 + ((lane >> 4) << 4);
                uint32_t off = SMEM_SWIZZLE_128B((uint32_t)(row * 128 + col));
                ldsm_x4(ah[mt], base + off);
                ldsm_x4(al[mt], base + TILE_B + off);
            }
#pragma unroll
            for (int p = 0; p < 4; p++) {
                int row = warp_n * 64 + p * 16 + (lane & 7) + (((lane >> 4) & 1) << 3);
                int col = kk * 32 + (((lane >> 3) & 1) << 4);
                uint32_t off = SMEM_SWIZZLE_128B((uint32_t)(row * 128 + col));
                uint32_t bh[4], bl[4];
                ldsm_x4(bh, base + 2 * TILE_B + off);
                ldsm_x4(bl, base + 3 * TILE_B + off);
#pragma unroll
                for (int mt = 0; mt < 2; mt++)
#pragma unroll
                    for (int n2 = 0; n2 < 2; n2++) {
                        mma_16<BF16>(chunk[mt][2 * p + n2], ah[mt], bl[2 * n2], bl[2 * n2 + 1]);
                        mma_16<BF16>(chunk[mt][2 * p + n2], al[mt], bh[2 * n2], bh[2 * n2 + 1]);
                    }
            }
        }
#pragma unroll
        for (int a = 0; a < 2; a++)
#pragma unroll
            for (int b = 0; b < 8; b++)
#pragma unroll
                for (int cc = 0; cc < 4; cc++)
                    master[a][b][cc] = fmaf(chunk[a][b][cc], mergeScale, master[a][b][cc]);

        // ---- pass B: h*h ----
#pragma unroll
        for (int a = 0; a < 2; a++)
#pragma unroll
            for (int b = 0; b < 8; b++)
#pragma unroll
                for (int cc = 0; cc < 4; cc++) chunk[a][b][cc] = 0.0f;

#pragma unroll
        for (int kk = 0; kk < 4; kk++) {
            uint32_t ah[2][4];
#pragma unroll
            for (int mt = 0; mt < 2; mt++) {
                int row = warp_m * 32 + mt * 16 + (lane & 15);
                int col = kk * 32 + ((lane >> 4) << 4);
                uint32_t off = SMEM_SWIZZLE_128B((uint32_t)(row * 128 + col));
                ldsm_x4(ah[mt], base + off);
            }
#pragma unroll
            for (int p = 0; p < 4; p++) {
                int row = warp_n * 64 + p * 16 + (lane & 7) + (((lane >> 4) & 1) << 3);
                int col = kk * 32 + (((lane >> 3) & 1) << 4);
                uint32_t off = SMEM_SWIZZLE_128B((uint32_t)(row * 128 + col));
                uint32_t bh[4];
                ldsm_x4(bh, base + 2 * TILE_B + off);
#pragma unroll
                for (int mt = 0; mt < 2; mt++)
#pragma unroll
                    for (int n2 = 0; n2 < 2; n2++)
                        mma_16<BF16>(chunk[mt][2 * p + n2], ah[mt], bh[2 * n2], bh[2 * n2 + 1]);
            }
        }
#pragma unroll
        for (int a = 0; a < 2; a++)
#pragma unroll
            for (int b = 0; b < 8; b++)
#pragma unroll
                for (int cc = 0; cc < 4; cc++) master[a][b][cc] += chunk[a][b][cc];

        __syncthreads();
    }

    // ---- epilogue ----
    float2 bcol[8];
#pragma unroll
    for (int nt = 0; nt < 8; nt++) {
        int cbase = n0 + warp_n * 64 + nt * 8 + (lane & 3) * 2;
        bcol[nt].x = __ldg(bias + cbase);
        bcol[nt].y = __ldg(bias + cbase + 1);
    }
#pragma unroll
    for (int mt = 0; mt < 2; mt++) {
        int r0 = m0 + warp_m * 32 + mt * 16 + (lane >> 2);
#pragma unroll
        for (int nt = 0; nt < 8; nt++) {
            int cbase = n0 + warp_n * 64 + nt * 8 + (lane & 3) * 2;
            float2 v0 = { master[mt][nt][0] + bcol[nt].x, master[mt][nt][1] + bcol[nt].y };
            float2 v1 = { master[mt][nt][2] + bcol[nt].x, master[mt][nt][3] + bcol[nt].y };
            *reinterpret_cast<float2*>(O + (size_t)r0 * N + cbase) = v0;
            *reinterpret_cast<float2*>(O + (size_t)(r0 + 8) * N + cbase) = v1;
        }
    }
}

// ---------------------------------------------------------------------------
// Gram kernel (R9): Gkk[u][t]=k_u.k_t, Gqk[u][t]=k_u.q_t per (batch, chunk).
// ---------------------------------------------------------------------------
__global__ __launch_bounds__(256) void gram_kernel(
    const float* __restrict__ qkv, float* __restrict__ G)
{
    const int blk = blockIdx.x;               // b*NCHUNK + c
    const int b = blk >> 7, c = blk & (NCHUNK - 1);
    const int u = threadIdx.x >> 4, t = threadIdx.x & 15;
    const float* basep = qkv + ((size_t)b * SS + c * SCAN_CH) * NQKV;
    const float4* ku = (const float4*)(basep + u * NQKV + 128);
    const float4* kt = (const float4*)(basep + t * NQKV + 128);
    const float4* qt = (const float4*)(basep + t * NQKV);
    float skk = 0.0f, sqk = 0.0f;
#pragma unroll 8
    for (int j = 0; j < 32; j++) {
        float4 a = __ldg(ku + j), bk = __ldg(kt + j), bq = __ldg(qt + j);
        skk += a.x * bk.x + a.y * bk.y + a.z * bk.z + a.w * bk.w;
        sqk += a.x * bq.x + a.y * bq.y + a.z * bq.z + a.w * bq.w;
    }
    float* go = G + (size_t)blk * 512;
    go[u * 16 + t] = skk;
    go[256 + u * 16 + t] = sqk;
}

// ---------------------------------------------------------------------------
// Chunked delta-rule scan (R9, byte-identical): fp32 y output.
// ---------------------------------------------------------------------------
#define QKV_F   (SCAN_CH * NQKV)             // 6144 floats
#define STAGE_F (QKV_F + 512)
#define SCAN_SMEM (2 * STAGE_F * 4)          // 53248 bytes

__global__ __launch_bounds__(256) void titan_scan(
    const float* __restrict__ qkv, const float* __restrict__ G,
    const float* __restrict__ state, const float* __restrict__ lr_ptr,
    float* __restrict__ ys, float* __restrict__ wfin)
{
    extern __shared__ float smemf[];
    const int tid  = threadIdx.x;
    const int warp = tid >> 5;
    const int lane = tid & 31;
    const int b    = blockIdx.x >> 4;
    const int i    = ((blockIdx.x & 15) << 3) + warp;

    const float lr = *lr_ptr;
    const float* base  = qkv + (size_t)b * SS * NQKV;
    const float* gbase = G + (size_t)b * NCHUNK * 512;
    float* yb = ys + (size_t)b * SS * HDV + i;

    const uint32_t s0 = smem_to_u32(smemf);
    auto stage = [&](int c) {
        if (c < NCHUNK) {
            const char* g = (const char*)(base + (size_t)c * QKV_F);
            const uint32_t sb = s0 + (uint32_t)(c & 1) * (STAGE_F * 4);
#pragma unroll
            for (int it = 0; it < 6; it++) {
                int idx = tid + it * 256;
                CP_ASYNC_CG(sb + idx * 16, g + idx * 16);
            }
            if (tid < 128)
                CP_ASYNC_CG(sb + QKV_F * 4 + tid * 16,
                            (const char*)(gbase + (size_t)c * 512) + tid * 16);
        }
    };
    stage(0); CP_COMMIT();
    stage(1); CP_COMMIT();

    float4 w4 = *reinterpret_cast<const float4*>(
        state + ((size_t)b * HDV + i) * HDV + lane * 4);

    for (int c = 0; c < NCHUNK; c++) {
        CP_WAIT_1();
        __syncthreads();
        const float* sb  = smemf + (c & 1) * STAGE_F;
        const float* gkk = sb + QKV_F;
        const float* gqk = gkk + 256;

        float Bv[SCAN_CH], e[SCAN_CH];
        float Asel = 0.0f;

        // ---- P1: parallel W0 dots ----
#pragma unroll
        for (int t = 0; t < SCAN_CH; t++) {
            const float* row = sb + t * NQKV;
            float4 q = *reinterpret_cast<const float4*>(row + lane * 4);
            float4 k = *reinterpret_cast<const float4*>(row + 128 + lane * 4);
            float a  = w4.x * q.x + w4.y * q.y + w4.z * q.z + w4.w * q.w;
            float bb = w4.x * k.x + w4.y * k.y + w4.z * k.z + w4.w * k.w;
#pragma unroll
            for (int o = 16; o > 0; o >>= 1) {
                a  += __shfl_xor_sync(0xffffffffu, a,  o);
                bb += __shfl_xor_sync(0xffffffffu, bb, o);
            }
            Bv[t] = bb;
            if (lane == t) Asel = a;
        }

        // ---- P2: serial triangular recursion (all lanes redundant) ----
#pragma unroll
        for (int t = 0; t < SCAN_CH; t++) {
            float acc = Bv[t];
#pragma unroll
            for (int u = 0; u < SCAN_CH; u++)
                if (u < t) acc = fmaf(-e[u], gkk[u * 16 + t], acc);
            e[t] = lr * (acc - sb[t * NQKV + 256 + i]);
        }

        // ---- P3a: outputs (lane t < 16 computes y_t) ----
        if (lane < SCAN_CH) {
            float dq = Asel;
#pragma unroll
            for (int u = 0; u < SCAN_CH - 1; u++)
                if (u < lane) dq = fmaf(-e[u], gqk[u * 16 + lane], dq);
            yb[(size_t)(c * SCAN_CH + lane) * HDV] = dq;
        }

        // ---- P3b: W update ----
#pragma unroll
        for (int u = 0; u < SCAN_CH; u++) {
            float4 k = *reinterpret_cast<const float4*>(sb + u * NQKV + 128 + lane * 4);
            w4.x = fmaf(-e[u], k.x, w4.x);
            w4.y = fmaf(-e[u], k.y, w4.y);
            w4.z = fmaf(-e[u], k.z, w4.z);
            w4.w = fmaf(-e[u], k.w, w4.w);
        }

        __syncthreads();
        stage(c + 2); CP_COMMIT();
    }

    *reinterpret_cast<float4*>(wfin + ((size_t)b * HDV + i) * HDV + lane * 4) = w4;
}

// ---------------------------------------------------------------------------
// Launch: R9 pipeline; ONLY change = weight prep on a side stream
// overlapping split_x. Scan runs alone (no co-scheduled work).
// ---------------------------------------------------------------------------
extern "C" void kernel_launch(void* const* d_in, const int* in_sizes, int n_in,
                              void* d_out, int out_size)
{
    const float* x     = (const float*)d_in[0];
    const float* state = (const float*)d_in[1];
    const float* Wq    = (const float*)d_in[2];
    const float* bq    = (const float*)d_in[3];
    const float* Wk    = (const float*)d_in[4];
    const float* bk    = (const float*)d_in[5];
    const float* Wv    = (const float*)d_in[6];
    const float* bv    = (const float*)d_in[7];
    const float* Wo    = (const float*)d_in[8];
    const float* bo    = (const float*)d_in[9];
    const float* lr    = (const float*)d_in[10];
    float* out = (float*)d_out;

    __half *xh, *xl, *wqkvh, *wqkvl;
    __nv_bfloat16 *yh, *yl, *woh, *wol;
    float *bqkv, *gqkv, *gy, *gws, *gG;
    cudaGetSymbolAddress((void**)&xh, g_xh);
    cudaGetSymbolAddress((void**)&xl, g_xl);
    cudaGetSymbolAddress((void**)&yh, g_yh);
    cudaGetSymbolAddress((void**)&yl, g_yl);
    cudaGetSymbolAddress((void**)&wqkvh, g_wqkvh);
    cudaGetSymbolAddress((void**)&wqkvl, g_wqkvl);
    cudaGetSymbolAddress((void**)&woh, g_woh);
    cudaGetSymbolAddress((void**)&wol, g_wol);
    cudaGetSymbolAddress((void**)&bqkv, g_bqkv);
    cudaGetSymbolAddress((void**)&gqkv, g_qkv);
    cudaGetSymbolAddress((void**)&gy, g_y);
    cudaGetSymbolAddress((void**)&gws, g_wfin_scratch);
    cudaGetSymbolAddress((void**)&gG, g_G);

    const size_t out_elems  = (size_t)BB * SS * DIMV;
    const size_t wfin_elems = (size_t)BB * HDV * HDV;
    float* wfin = ((size_t)out_size >= out_elems + wfin_elems)
                      ? (out + out_elems) : gws;

    cudaFuncSetAttribute(mma_gemm<false>, cudaFuncAttributeMaxDynamicSharedMemorySize, SMEM_GEMM);
    cudaFuncSetAttribute(mma_gemm<true>,  cudaFuncAttributeMaxDynamicSharedMemorySize, SMEM_GEMM);
    cudaFuncSetAttribute(titan_scan,      cudaFuncAttributeMaxDynamicSharedMemorySize, SCAN_SMEM);

    // one-time stream/event handles (resources only; identical work per call)
    static cudaStream_t s1 = nullptr;
    static cudaEvent_t evFork = nullptr, evW = nullptr, evWo = nullptr;
    if (!s1) {
        cudaStreamCreateWithFlags(&s1, cudaStreamNonBlocking);
        cudaEventCreateWithFlags(&evFork, cudaEventDisableTiming);
        cudaEventCreateWithFlags(&evW,    cudaEventDisableTiming);
        cudaEventCreateWithFlags(&evWo,   cudaEventDisableTiming);
    }

    // ---- fork ----
    cudaEventRecord(evFork, 0);
    cudaStreamWaitEvent(s1, evFork, 0);

    // ---- s1: weight prep (overlaps split_x on the main stream) ----
    {
        int kn = DIMV * HDV;
        transpose_split2f_kernel<<<(kn + 255) / 256, 256, 0, s1>>>(
            Wq, wqkvh + 0 * HDV * DIMV, wqkvl + 0 * HDV * DIMV, DIMV, HDV);
        transpose_split2f_kernel<<<(kn + 255) / 256, 256, 0, s1>>>(
            Wk, wqkvh + 1 * HDV * DIMV, wqkvl + 1 * HDV * DIMV, DIMV, HDV);
        transpose_split2f_kernel<<<(kn + 255) / 256, 256, 0, s1>>>(
            Wv, wqkvh + 2 * HDV * DIMV, wqkvl + 2 * HDV * DIMV, DIMV, HDV);
        concat_bias_kernel<<<1, 128, 0, s1>>>(bq, bk, bv, bqkv);
        cudaEventRecord(evW, s1);
        transpose_split2b_kernel<<<(kn + 255) / 256, 256, 0, s1>>>(Wo, woh, wol, HDV, DIMV);
        cudaEventRecord(evWo, s1);
    }

    // ---- main: split x -> QKV GEMM -> gram -> scan -> split y -> out GEMM ----
    {
        int n4 = MTOK * DIMV / 4;
        split2f_kernel<<<(n4 + 255) / 256, 256>>>(x, xh, xl, n4);
    }
    cudaStreamWaitEvent(0, evW, 0);
    mma_gemm<false><<<dim3(MTOK / 128, NQKV / 128), 256, SMEM_GEMM>>>(
        xh, xl, wqkvh, wqkvl, bqkv, gqkv, NQKV, DIMV);
    gram_kernel<<<BB * NCHUNK, 256>>>(gqkv, gG);
    titan_scan<<<128, 256, SCAN_SMEM>>>(gqkv, gG, state, lr, gy, wfin);

    {
        int n4 = MTOK * HDV / 4;
        split2b_kernel<<<(n4 + 255) / 256, 256>>>(gy, yh, yl, n4);
    }
    cudaStreamWaitEvent(0, evWo, 0);
    mma_gemm<true><<<dim3(MTOK / 128, DIMV / 128), 256, SMEM_GEMM>>>(
        yh, yl, woh, wol, bo, out, DIMV, HDV);
}